// round 4
// baseline (speedup 1.0000x reference)
#include <cuda_runtime.h>
#include <cstdint>

// HeteroGCNConv: 3-layer weighted GCN.
// Inputs: x[N*128] f32, edge_weight[E] f32, W[L*128*128] f32, b[L*128] f32,
//         src[E] i32, dst[E] i32. Output: [N*128] f32.
//
// dst-CSR built once per launch; per layer: 128x128-tile fp32 GEMM (8x8 reg
// tile/thread) then warp-per-node gather-SpMM (+bias+ELU), h2 L2-resident.
// Launch order arranged so ncu (-s 5) profiles gemm_kernel.

#define D 128
#define NMAX 100000
#define EMAX 1600000
#define CHUNK 1024
#define NCH_MAX ((NMAX + CHUNK - 1) / CHUNK)

__device__ float g_deg_src[NMAX];
__device__ float g_deg_dst[NMAX];
__device__ int   g_cnt[NMAX];
__device__ int   g_fill[NMAX];
__device__ int   g_row_ptr[NMAX + 1];
__device__ int   g_chunk_sum[NCH_MAX + 1];
__device__ int2  g_cv[EMAX];                    // (src_node, bitcast(norm_weight))
__device__ float g_hA[(size_t)NMAX * D];        // layer output buffer
__device__ float g_h2[(size_t)NMAX * D];        // post-GEMM buffer

// ---------------- precompute ----------------

__global__ void zero_kernel(int n) {
    int i = blockIdx.x * blockDim.x + threadIdx.x;
    if (i < n) {
        g_deg_src[i] = 0.f;
        g_deg_dst[i] = 0.f;
        g_cnt[i] = 0;
        g_fill[i] = 0;
    }
}

__global__ void deg_kernel(const float* __restrict__ ew,
                           const int* __restrict__ src,
                           const int* __restrict__ dst, int e) {
    int i = blockIdx.x * blockDim.x + threadIdx.x;
    if (i < e) {
        float w = ew[i];
        atomicAdd(&g_deg_src[src[i]], w);
        atomicAdd(&g_deg_dst[dst[i]], w);
        atomicAdd(&g_cnt[dst[i]], 1);
    }
}

// per-chunk sums of g_cnt
__global__ void scan_a(int n) {
    __shared__ int sh[256];
    int t = threadIdx.x;
    int base = blockIdx.x * CHUNK;
    int s = 0;
    for (int j = t; j < CHUNK; j += 256) {
        int i = base + j;
        s += (i < n) ? g_cnt[i] : 0;
    }
    sh[t] = s;
    __syncthreads();
    for (int off = 128; off > 0; off >>= 1) {
        if (t < off) sh[t] += sh[t + off];
        __syncthreads();
    }
    if (t == 0) g_chunk_sum[blockIdx.x] = sh[0];
}

// intra-chunk scan; each block computes its own chunk-prefix inline (nchunks ~98)
__global__ void scan_c(int n, int nchunks) {
    __shared__ int sh[CHUNK];
    __shared__ int s_off;
    int t = threadIdx.x;
    int i = blockIdx.x * CHUNK + t;

    if (t == 0) {
        int run = 0;
        for (int c = 0; c < (int)blockIdx.x; ++c) run += g_chunk_sum[c];
        s_off = run;
        if ((int)blockIdx.x == nchunks - 1) {
            int tot = run;
            for (int c = blockIdx.x; c < nchunks; ++c) tot += g_chunk_sum[c];
            g_row_ptr[n] = tot;   // == E
        }
    }

    int v = (i < n) ? g_cnt[i] : 0;
    sh[t] = v;
    __syncthreads();
    for (int off = 1; off < CHUNK; off <<= 1) {
        int x = (t >= off) ? sh[t - off] : 0;
        __syncthreads();
        sh[t] += x;
        __syncthreads();
    }
    if (i < n) g_row_ptr[i] = s_off + sh[t] - v;  // exclusive prefix
}

// fill CSR slots; symmetric norm weight inline
__global__ void fill_kernel(const float* __restrict__ ew,
                            const int* __restrict__ src,
                            const int* __restrict__ dst, int e) {
    int i = blockIdx.x * blockDim.x + threadIdx.x;
    if (i < e) {
        int s = src[i], d = dst[i];
        float nw = ew[i] * rsqrtf(g_deg_src[s] * g_deg_dst[d]);
        int pos = g_row_ptr[d] + atomicAdd(&g_fill[d], 1);
        g_cv[pos] = make_int2(s, __float_as_int(nw));
    }
}

// ---------------- per-layer GEMM: C[n,128] = A[n,128] @ W[128,128] ----------------
// 256 threads/block, block tile 128 rows x 128 cols, 8x8 register tile/thread.
// Inner loop: 10 LDS per 64 FFMA.

#define BM 128
#define KT 32

__global__ __launch_bounds__(256) void gemm_kernel(const float* __restrict__ Aext,
                                                   const float* __restrict__ Wl, int n) {
    const float* __restrict__ A = Aext ? Aext : g_hA;
    __shared__ __align__(16) float sA[BM][KT + 1];   // +1 pad: rows 0/8 hit distinct banks
    __shared__ __align__(16) float sW[KT][D];

    int t  = threadIdx.x;
    int tx = t & 15;          // col group: cols 8*tx .. 8*tx+7
    int ty = t >> 4;          // row group: rows 8*ty .. 8*ty+7
    int row0 = blockIdx.x * BM;
    int r0 = ty * 8;
    int c0 = tx * 8;

    float acc[8][8];
#pragma unroll
    for (int i = 0; i < 8; ++i)
#pragma unroll
        for (int j = 0; j < 8; ++j) acc[i][j] = 0.f;

    for (int kt = 0; kt < D; kt += KT) {
        // load A tile (128x32): 4096 floats, 256 threads x 4 float4
#pragma unroll
        for (int q = 0; q < 4; ++q) {
            int idx = (q * 256 + t) * 4;          // element index in tile
            int r = idx >> 5, c = idx & 31;
            int gr = row0 + r;
            float4 v = make_float4(0.f, 0.f, 0.f, 0.f);
            if (gr < n) v = *(const float4*)(A + (size_t)gr * D + kt + c);
            sA[r][c]     = v.x; sA[r][c + 1] = v.y;
            sA[r][c + 2] = v.z; sA[r][c + 3] = v.w;
        }
        // load W tile (32x128): 4096 floats
#pragma unroll
        for (int q = 0; q < 4; ++q) {
            int idx = (q * 256 + t) * 4;
            int r = idx >> 7, c = idx & 127;
            *(float4*)&sW[r][c] = *(const float4*)(Wl + (size_t)(kt + r) * D + c);
        }
        __syncthreads();

#pragma unroll
        for (int kk = 0; kk < KT; ++kk) {
            float4 w0 = *(const float4*)&sW[kk][c0];
            float4 w1 = *(const float4*)&sW[kk][c0 + 4];
            float a[8];
#pragma unroll
            for (int i = 0; i < 8; ++i) a[i] = sA[r0 + i][kk];
#pragma unroll
            for (int i = 0; i < 8; ++i) {
                acc[i][0] = fmaf(a[i], w0.x, acc[i][0]);
                acc[i][1] = fmaf(a[i], w0.y, acc[i][1]);
                acc[i][2] = fmaf(a[i], w0.z, acc[i][2]);
                acc[i][3] = fmaf(a[i], w0.w, acc[i][3]);
                acc[i][4] = fmaf(a[i], w1.x, acc[i][4]);
                acc[i][5] = fmaf(a[i], w1.y, acc[i][5]);
                acc[i][6] = fmaf(a[i], w1.z, acc[i][6]);
                acc[i][7] = fmaf(a[i], w1.w, acc[i][7]);
            }
        }
        __syncthreads();
    }

#pragma unroll
    for (int i = 0; i < 8; ++i) {
        int gr = row0 + r0 + i;
        if (gr < n) {
            float* dst = g_h2 + (size_t)gr * D + c0;
            *(float4*)dst       = make_float4(acc[i][0], acc[i][1], acc[i][2], acc[i][3]);
            *(float4*)(dst + 4) = make_float4(acc[i][4], acc[i][5], acc[i][6], acc[i][7]);
        }
    }
}

// ---------------- per-layer SpMM + bias + ELU: one warp per dst node ----------------

__global__ __launch_bounds__(256) void spmm_kernel(const float* __restrict__ bias,
                                                   float* __restrict__ outExt, int n) {
    float* __restrict__ out = outExt ? outExt : g_hA;
    int warp = (blockIdx.x * blockDim.x + threadIdx.x) >> 5;
    int lane = threadIdx.x & 31;
    if (warp >= n) return;

    int p   = g_row_ptr[warp];
    int end = g_row_ptr[warp + 1];
    int c4  = lane * 4;

    float4 acc = make_float4(0.f, 0.f, 0.f, 0.f);

    for (; p + 4 <= end; p += 4) {
        int2 c0 = g_cv[p + 0];
        int2 c1 = g_cv[p + 1];
        int2 c2 = g_cv[p + 2];
        int2 c3 = g_cv[p + 3];
        float4 h0  = *(const float4*)(g_h2 + (size_t)c0.x * D + c4);
        float4 h1  = *(const float4*)(g_h2 + (size_t)c1.x * D + c4);
        float4 h2v = *(const float4*)(g_h2 + (size_t)c2.x * D + c4);
        float4 h3  = *(const float4*)(g_h2 + (size_t)c3.x * D + c4);
        float v0 = __int_as_float(c0.y), v1 = __int_as_float(c1.y);
        float v2 = __int_as_float(c2.y), v3 = __int_as_float(c3.y);
        acc.x = fmaf(v0, h0.x, acc.x);  acc.y = fmaf(v0, h0.y, acc.y);
        acc.z = fmaf(v0, h0.z, acc.z);  acc.w = fmaf(v0, h0.w, acc.w);
        acc.x = fmaf(v1, h1.x, acc.x);  acc.y = fmaf(v1, h1.y, acc.y);
        acc.z = fmaf(v1, h1.z, acc.z);  acc.w = fmaf(v1, h1.w, acc.w);
        acc.x = fmaf(v2, h2v.x, acc.x); acc.y = fmaf(v2, h2v.y, acc.y);
        acc.z = fmaf(v2, h2v.z, acc.z); acc.w = fmaf(v2, h2v.w, acc.w);
        acc.x = fmaf(v3, h3.x, acc.x);  acc.y = fmaf(v3, h3.y, acc.y);
        acc.z = fmaf(v3, h3.z, acc.z);  acc.w = fmaf(v3, h3.w, acc.w);
    }
    for (; p < end; ++p) {
        int2 cv = g_cv[p];
        float v = __int_as_float(cv.y);
        const float4 hv = *(const float4*)(g_h2 + (size_t)cv.x * D + c4);
        acc.x = fmaf(v, hv.x, acc.x);
        acc.y = fmaf(v, hv.y, acc.y);
        acc.z = fmaf(v, hv.z, acc.z);
        acc.w = fmaf(v, hv.w, acc.w);
    }

    float4 bb = *(const float4*)(bias + c4);
    acc.x += bb.x; acc.y += bb.y; acc.z += bb.z; acc.w += bb.w;
    acc.x = acc.x > 0.f ? acc.x : expm1f(acc.x);
    acc.y = acc.y > 0.f ? acc.y : expm1f(acc.y);
    acc.z = acc.z > 0.f ? acc.z : expm1f(acc.z);
    acc.w = acc.w > 0.f ? acc.w : expm1f(acc.w);
    *(float4*)(out + (size_t)warp * D + c4) = acc;
}

// ---------------- launch ----------------

extern "C" void kernel_launch(void* const* d_in, const int* in_sizes, int n_in,
                              void* d_out, int out_size) {
    const float* x    = (const float*)d_in[0];
    const float* ew   = (const float*)d_in[1];
    const float* Wm   = (const float*)d_in[2];
    const float* bias = (const float*)d_in[3];
    const int*   src  = (const int*)d_in[4];
    const int*   dst  = (const int*)d_in[5];

    int E = in_sizes[1];
    int N = in_sizes[0] / D;
    int L = in_sizes[3] / D;
    int nchunks = (N + CHUNK - 1) / CHUNK;

    zero_kernel<<<(N + 255) / 256, 256>>>(N);                    // launch 0
    deg_kernel<<<(E + 255) / 256, 256>>>(ew, src, dst, E);       // launch 1
    scan_a<<<nchunks, 256>>>(N);                                 // launch 2
    scan_c<<<nchunks, CHUNK>>>(N, nchunks);                      // launch 3
    fill_kernel<<<(E + 255) / 256, 256>>>(ew, src, dst, E);      // launch 4

    const float* curExt = x;   // layer-0 input; nullptr => g_hA afterwards
    for (int l = 0; l < L; ++l) {
        gemm_kernel<<<(N + BM - 1) / BM, 256>>>(curExt, Wm + (size_t)l * D * D, N);  // launch 5 = layer-0 gemm
        float* outExt = (l == L - 1) ? (float*)d_out : nullptr;
        spmm_kernel<<<((size_t)N * 32 + 255) / 256, 256>>>(bias + (size_t)l * D, outExt, N);
        curExt = nullptr;
    }
}

// round 7
// speedup vs baseline: 1.0892x; 1.0892x over previous
#include <cuda_runtime.h>
#include <cstdint>

// HeteroGCNConv: 3-layer weighted GCN.
// Inputs: x[N*128] f32, edge_weight[E] f32, W[L*128*128] f32, b[L*128] f32,
//         src[E] i32, dst[E] i32. Output: [N*128] f32.
//
// dst-CSR built once per launch; per layer: 64x128-tile fp32 GEMM (8x4 reg
// tile/thread — proven config) then warp-per-node gather-SpMM (+bias+ELU),
// h2 L2-resident. gemm_0 hoisted to launch idx 3 so ncu profiles it.

#define D 128
#define NMAX 100000
#define EMAX 1600000
#define CHUNK 1024
#define NCH_MAX ((NMAX + CHUNK - 1) / CHUNK)

__device__ float g_deg_src[NMAX];
__device__ float g_deg_dst[NMAX];
__device__ int   g_cnt[NMAX];
__device__ int   g_fill[NMAX];
__device__ int   g_row_ptr[NMAX + 1];
__device__ int   g_chunk_sum[NCH_MAX + 1];
__device__ int2  g_cv[EMAX];                    // (src_node, bitcast(norm_weight))
__device__ float g_hA[(size_t)NMAX * D];        // layer output buffer
__device__ float g_h2[(size_t)NMAX * D];        // post-GEMM buffer

// ---------------- precompute ----------------

__global__ void zero_kernel(int n) {
    int i = blockIdx.x * blockDim.x + threadIdx.x;
    if (i < n) {
        g_deg_src[i] = 0.f;
        g_deg_dst[i] = 0.f;
        g_cnt[i] = 0;
        g_fill[i] = 0;
    }
}

__global__ void deg_kernel(const float* __restrict__ ew,
                           const int* __restrict__ src,
                           const int* __restrict__ dst, int e) {
    int i = blockIdx.x * blockDim.x + threadIdx.x;
    if (i < e) {
        float w = ew[i];
        atomicAdd(&g_deg_src[src[i]], w);
        atomicAdd(&g_deg_dst[dst[i]], w);
        atomicAdd(&g_cnt[dst[i]], 1);
    }
}

// per-chunk sums of g_cnt
__global__ void scan_a(int n) {
    __shared__ int sh[256];
    int t = threadIdx.x;
    int base = blockIdx.x * CHUNK;
    int s = 0;
    for (int j = t; j < CHUNK; j += 256) {
        int i = base + j;
        s += (i < n) ? g_cnt[i] : 0;
    }
    sh[t] = s;
    __syncthreads();
    for (int off = 128; off > 0; off >>= 1) {
        if (t < off) sh[t] += sh[t + off];
        __syncthreads();
    }
    if (t == 0) g_chunk_sum[blockIdx.x] = sh[0];
}

// intra-chunk scan; each block computes its own chunk-prefix inline (nchunks ~98)
__global__ void scan_c(int n, int nchunks) {
    __shared__ int sh[CHUNK];
    __shared__ int s_off;
    int t = threadIdx.x;
    int i = blockIdx.x * CHUNK + t;

    if (t == 0) {
        int run = 0;
        for (int c = 0; c < (int)blockIdx.x; ++c) run += g_chunk_sum[c];
        s_off = run;
        if ((int)blockIdx.x == nchunks - 1) {
            int tot = run;
            for (int c = blockIdx.x; c < nchunks; ++c) tot += g_chunk_sum[c];
            g_row_ptr[n] = tot;   // == E
        }
    }

    int v = (i < n) ? g_cnt[i] : 0;
    sh[t] = v;
    __syncthreads();
    for (int off = 1; off < CHUNK; off <<= 1) {
        int x = (t >= off) ? sh[t - off] : 0;
        __syncthreads();
        sh[t] += x;
        __syncthreads();
    }
    if (i < n) g_row_ptr[i] = s_off + sh[t] - v;  // exclusive prefix
}

// fill CSR slots; symmetric norm weight inline
__global__ void fill_kernel(const float* __restrict__ ew,
                            const int* __restrict__ src,
                            const int* __restrict__ dst, int e) {
    int i = blockIdx.x * blockDim.x + threadIdx.x;
    if (i < e) {
        int s = src[i], d = dst[i];
        float nw = ew[i] * rsqrtf(g_deg_src[s] * g_deg_dst[d]);
        int pos = g_row_ptr[d] + atomicAdd(&g_fill[d], 1);
        g_cv[pos] = make_int2(s, __float_as_int(nw));
    }
}

// ---------------- per-layer GEMM: C[n,128] = A[n,128] @ W[128,128] ----------------
// Proven config from the 506.5us run: 256 threads, 64-row tile, 8x4 acc/thread.

#define BM 64
#define KT 32

__global__ __launch_bounds__(256) void gemm_kernel(const float* __restrict__ Aext,
                                                   const float* __restrict__ Wl, int n) {
    const float* __restrict__ A = Aext ? Aext : g_hA;
    __shared__ __align__(16) float sA[BM][KT];
    __shared__ __align__(16) float sW[KT][D];

    int t = threadIdx.x;
    int tx = t & 31;       // col group: cols 4*tx..4*tx+3
    int ty = t >> 5;       // warp id: rows ty*8..ty*8+7
    int row0 = blockIdx.x * BM;

    float4 acc[8];
#pragma unroll
    for (int i = 0; i < 8; ++i) acc[i] = make_float4(0.f, 0.f, 0.f, 0.f);

    for (int kt = 0; kt < D; kt += KT) {
        // load A tile (64x32)
#pragma unroll
        for (int idx = t; idx < BM * KT; idx += 256) {
            int r = idx >> 5, c = idx & 31;
            int gr = row0 + r;
            sA[r][c] = (gr < n) ? A[(size_t)gr * D + kt + c] : 0.f;
        }
        // load W tile (32x128)
#pragma unroll
        for (int idx = t; idx < KT * D; idx += 256) {
            int r = idx >> 7, c = idx & 127;
            sW[r][c] = Wl[(size_t)(kt + r) * D + c];
        }
        __syncthreads();
#pragma unroll
        for (int kk = 0; kk < KT; ++kk) {
            float4 w4 = *(const float4*)&sW[kk][tx * 4];
#pragma unroll
            for (int i = 0; i < 8; ++i) {
                float a = sA[ty * 8 + i][kk];   // warp-broadcast LDS
                acc[i].x = fmaf(a, w4.x, acc[i].x);
                acc[i].y = fmaf(a, w4.y, acc[i].y);
                acc[i].z = fmaf(a, w4.z, acc[i].z);
                acc[i].w = fmaf(a, w4.w, acc[i].w);
            }
        }
        __syncthreads();
    }
#pragma unroll
    for (int i = 0; i < 8; ++i) {
        int gr = row0 + ty * 8 + i;
        if (gr < n) *(float4*)&g_h2[(size_t)gr * D + tx * 4] = acc[i];
    }
}

// ---------------- per-layer SpMM + bias + ELU: one warp per dst node ----------------

__global__ __launch_bounds__(256) void spmm_kernel(const float* __restrict__ bias,
                                                   float* __restrict__ outExt, int n) {
    float* __restrict__ out = outExt ? outExt : g_hA;
    int warp = (blockIdx.x * blockDim.x + threadIdx.x) >> 5;
    int lane = threadIdx.x & 31;
    if (warp >= n) return;

    int p   = g_row_ptr[warp];
    int end = g_row_ptr[warp + 1];
    int c4  = lane * 4;

    float4 acc = make_float4(0.f, 0.f, 0.f, 0.f);

    for (; p + 4 <= end; p += 4) {
        int2 c0 = g_cv[p + 0];
        int2 c1 = g_cv[p + 1];
        int2 c2 = g_cv[p + 2];
        int2 c3 = g_cv[p + 3];
        float4 h0  = *(const float4*)(g_h2 + (size_t)c0.x * D + c4);
        float4 h1  = *(const float4*)(g_h2 + (size_t)c1.x * D + c4);
        float4 h2v = *(const float4*)(g_h2 + (size_t)c2.x * D + c4);
        float4 h3  = *(const float4*)(g_h2 + (size_t)c3.x * D + c4);
        float v0 = __int_as_float(c0.y), v1 = __int_as_float(c1.y);
        float v2 = __int_as_float(c2.y), v3 = __int_as_float(c3.y);
        acc.x = fmaf(v0, h0.x, acc.x);  acc.y = fmaf(v0, h0.y, acc.y);
        acc.z = fmaf(v0, h0.z, acc.z);  acc.w = fmaf(v0, h0.w, acc.w);
        acc.x = fmaf(v1, h1.x, acc.x);  acc.y = fmaf(v1, h1.y, acc.y);
        acc.z = fmaf(v1, h1.z, acc.z);  acc.w = fmaf(v1, h1.w, acc.w);
        acc.x = fmaf(v2, h2v.x, acc.x); acc.y = fmaf(v2, h2v.y, acc.y);
        acc.z = fmaf(v2, h2v.z, acc.z); acc.w = fmaf(v2, h2v.w, acc.w);
        acc.x = fmaf(v3, h3.x, acc.x);  acc.y = fmaf(v3, h3.y, acc.y);
        acc.z = fmaf(v3, h3.z, acc.z);  acc.w = fmaf(v3, h3.w, acc.w);
    }
    for (; p < end; ++p) {
        int2 cv = g_cv[p];
        float v = __int_as_float(cv.y);
        const float4 hv = *(const float4*)(g_h2 + (size_t)cv.x * D + c4);
        acc.x = fmaf(v, hv.x, acc.x);
        acc.y = fmaf(v, hv.y, acc.y);
        acc.z = fmaf(v, hv.z, acc.z);
        acc.w = fmaf(v, hv.w, acc.w);
    }

    float4 bb = *(const float4*)(bias + c4);
    acc.x += bb.x; acc.y += bb.y; acc.z += bb.z; acc.w += bb.w;
    acc.x = acc.x > 0.f ? acc.x : expm1f(acc.x);
    acc.y = acc.y > 0.f ? acc.y : expm1f(acc.y);
    acc.z = acc.z > 0.f ? acc.z : expm1f(acc.z);
    acc.w = acc.w > 0.f ? acc.w : expm1f(acc.w);
    *(float4*)(out + (size_t)warp * D + c4) = acc;
}

// ---------------- launch ----------------

extern "C" void kernel_launch(void* const* d_in, const int* in_sizes, int n_in,
                              void* d_out, int out_size) {
    const float* x    = (const float*)d_in[0];
    const float* ew   = (const float*)d_in[1];
    const float* Wm   = (const float*)d_in[2];
    const float* bias = (const float*)d_in[3];
    const int*   src  = (const int*)d_in[4];
    const int*   dst  = (const int*)d_in[5];

    int E = in_sizes[1];
    int N = in_sizes[0] / D;
    int L = in_sizes[3] / D;
    int nchunks = (N + CHUNK - 1) / CHUNK;

    zero_kernel<<<(N + 255) / 256, 256>>>(N);                    // idx 0
    deg_kernel<<<(E + 255) / 256, 256>>>(ew, src, dst, E);       // idx 1
    scan_a<<<nchunks, 256>>>(N);                                 // idx 2
    // layer-0 GEMM depends only on x and W — hoisted here so ncu profiles it.
    gemm_kernel<<<(N + BM - 1) / BM, 256>>>(x, Wm, N);           // idx 3 (profiled)
    scan_c<<<nchunks, CHUNK>>>(N, nchunks);                      // idx 4
    fill_kernel<<<(E + 255) / 256, 256>>>(ew, src, dst, E);      // idx 5

    for (int l = 0; l < L; ++l) {
        if (l > 0)
            gemm_kernel<<<(N + BM - 1) / BM, 256>>>(nullptr, Wm + (size_t)l * D * D, N);
        float* outExt = (l == L - 1) ? (float*)d_out : nullptr;
        spmm_kernel<<<((size_t)N * 32 + 255) / 256, 256>>>(bias + (size_t)l * D, outExt, N);
    }
}